// round 2
// baseline (speedup 1.0000x reference)
#include <cuda_runtime.h>

// LIF activation recurrence:
//   keep = (1 - Vm > 0)
//   Vm   = relu(x_t + (1 - w_leak) * Vm * keep)
//   out  = (Vm - 1 > 0) ? 1 : 0
// x: [B=128, T=1000, C=512] f32, w_leak: [C] f32, out: [B, T, C] f32.
// Sequential in T, parallel over B*C = 65536 lanes. Pure HBM streaming.

#define LIF_B 128
#define LIF_T 1000
#define LIF_C 512
#define LIF_U 8  // unroll / prefetch depth per buffer

__global__ __launch_bounds__(256, 8)
void lif_kernel(const float* __restrict__ x,
                const float* __restrict__ w_leak,
                float* __restrict__ out) {
    const int i = blockIdx.x * blockDim.x + threadIdx.x;  // 0 .. B*C-1
    const int c = i & (LIF_C - 1);
    const int b = i >> 9;  // log2(C) = 9

    const float wl = 1.0f - w_leak[c];
    const size_t base = (size_t)b * LIF_T * LIF_C + c;
    const float* xp = x + base;
    float*       op = out + base;

    float vm = 0.0f;

    // Two fixed-name register buffers (no dynamic indexing -> no local spill).
    float bufA[LIF_U], bufB[LIF_U];

    // Prime buffer A with t = 0..U-1
    #pragma unroll
    for (int u = 0; u < LIF_U; u++) bufA[u] = xp[u * LIF_C];

    // Main loop: 62 iterations x 16 timesteps = t 0..991.
    // Each half prefetches the *other* buffer one chunk ahead, so there are
    // always ~U independent loads in flight per thread while computing.
    #pragma unroll 1
    for (int t = 0; t < LIF_T - LIF_U; t += 2 * LIF_U) {
        // prefetch t+U .. t+2U-1 into B
        #pragma unroll
        for (int u = 0; u < LIF_U; u++) bufB[u] = xp[(t + LIF_U + u) * LIF_C];

        // compute t .. t+U-1 from A
        #pragma unroll
        for (int u = 0; u < LIF_U; u++) {
            float vk = (vm < 1.0f) ? vm : 0.0f;                      // hard-reset gate
            vm = fmaxf(__fadd_rn(bufA[u], __fmul_rn(wl, vk)), 0.0f); // relu, unfused mul+add
            op[(t + u) * LIF_C] = (vm > 1.0f) ? 1.0f : 0.0f;         // spike
        }

        // prefetch t+2U .. t+3U-1 into A (last iter loads t=992..999)
        #pragma unroll
        for (int u = 0; u < LIF_U; u++) bufA[u] = xp[(t + 2 * LIF_U + u) * LIF_C];

        // compute t+U .. t+2U-1 from B
        #pragma unroll
        for (int u = 0; u < LIF_U; u++) {
            float vk = (vm < 1.0f) ? vm : 0.0f;
            vm = fmaxf(__fadd_rn(bufB[u], __fmul_rn(wl, vk)), 0.0f);
            op[(t + LIF_U + u) * LIF_C] = (vm > 1.0f) ? 1.0f : 0.0f;
        }
    }

    // Tail: t = 992..999 is already sitting in bufA from the last prefetch.
    #pragma unroll
    for (int u = 0; u < LIF_U; u++) {
        float vk = (vm < 1.0f) ? vm : 0.0f;
        vm = fmaxf(__fadd_rn(bufA[u], __fmul_rn(wl, vk)), 0.0f);
        op[(LIF_T - LIF_U + u) * LIF_C] = (vm > 1.0f) ? 1.0f : 0.0f;
    }
}

extern "C" void kernel_launch(void* const* d_in, const int* in_sizes, int n_in,
                              void* d_out, int out_size) {
    const float* x      = (const float*)d_in[0];   // [B, T, C] f32
    const float* w_leak = (const float*)d_in[1];   // [C] f32
    float* out = (float*)d_out;                    // [B, T, C] f32

    const int total = LIF_B * LIF_C;               // 65536 lanes
    lif_kernel<<<total / 256, 256>>>(x, w_leak, out);
}